// round 1
// baseline (speedup 1.0000x reference)
#include <cuda_runtime.h>
#include <math.h>

#define F 256
#define NB 1024

// Partial sums: [4][NB][F] = 4 MB static scratch (no allocations allowed).
__device__ float g_part[4 * NB * F];

__global__ __launch_bounds__(256) void mdl_pass1(
    const float* __restrict__ res,
    const float* __restrict__ lambda1,
    const float* __restrict__ lambda2,
    int rows_per_block, int B)
{
    const int f = threadIdx.x;            // feature index 0..255
    const float l1 = lambda1[f];
    const float l2v = lambda2[f];
    const float lamP = l1;
    const float lamN = 2.0f - l2v;
    // reciprocals hoisted out of the loop (division is expensive)
    const float rlamP = 1.0f / lamP;
    const float rlamN = 1.0f / lamN;
    const bool okP = fabsf(l1) <= 1.9f;
    const bool okN = fabsf(l2v) <= 1.9f;
    const bool tinyP = fabsf(lamP) < 1e-8f;
    const bool tinyN = fabsf(lamN) < 1e-8f;

    const int r0 = blockIdx.x * rows_per_block;
    int r1 = r0 + rows_per_block;
    if (r1 > B) r1 = B;

    float cnt = 0.0f, sy = 0.0f, sy2 = 0.0f, slj = 0.0f;

    const float* p = res + (size_t)r0 * F + f;

#pragma unroll 4
    for (int r = r0; r < r1; ++r, p += F) {
        const float x = *p;
        const bool pos = (x >= 0.0f);

        // unified transform:
        //   pos: a = 1 + min(x,1000),  lam = lambda1,      y = +expm1(lam*t)/lam
        //   neg: a = 1 - max(x,-.989), lam = 2 - lambda2,  y = -expm1(lam*t)/lam
        //   lj  = (lam - 1) * t  in both branches
        const float a    = pos ? (1.0f + fminf(x, 1000.0f))
                               : (1.0f - fmaxf(x, -0.989f));
        const float lam  = pos ? lamP : lamN;
        const float rlam = pos ? rlamP : rlamN;
        const bool tiny  = pos ? tinyP : tinyN;
        const bool safe  = pos ? ((x <= 1000.0f) && okP)
                               : ((x > -0.99f) && okN);

        const float t = __logf(a);
        const float u = lam * t;

        // branchless expm1: Taylor for small |u|, __expf path otherwise
        const float e_poly = u * (1.0f + u * (0.5f + u * (0.16666667f
                              + u * (0.041666668f + u * 0.008333334f))));
        const float e_exp  = __expf(u) - 1.0f;
        const float e = (fabsf(u) < 0.25f) ? e_poly : e_exp;

        float y = tiny ? t : (e * rlam);
        if (!pos) y = -y;
        const float lj = (lam - 1.0f) * t;

        if (safe) {
            cnt += 1.0f;
            sy  += y;
            sy2 += y * y;
            slj += lj;
        }
    }

    const int base = blockIdx.x * F + f;
    g_part[0 * NB * F + base] = cnt;
    g_part[1 * NB * F + base] = sy;
    g_part[2 * NB * F + base] = sy2;
    g_part[3 * NB * F + base] = slj;
}

__global__ __launch_bounds__(256) void mdl_pass2(
    const float* __restrict__ resolutions,
    float* __restrict__ out, int B)
{
    const int f = threadIdx.x;  // one feature per thread

    double cnt = 0.0, sy = 0.0, sy2 = 0.0, slj = 0.0;
    for (int b = 0; b < NB; ++b) {
        const int base = b * F + f;
        cnt += (double)g_part[0 * NB * F + base];
        sy  += (double)g_part[1 * NB * F + base];
        sy2 += (double)g_part[2 * NB * F + base];
        slj += (double)g_part[3 * NB * F + base];
    }

    const double LN2 = 0.6931471805599453;
    const double LOG2_2PIE = 2.0470955851806783;  // 0.5*log2(2*pi*e)

    const double Bd   = (double)B;
    const double nf   = cnt;
    const double nexc = Bd - nf;
    const double denom = fmax(nf, 1.0);
    const double mean = sy / denom;
    // sum(fin*(y-mean)^2) = sy2 - 2*mean*sy + mean^2*nf
    double var = (sy2 - 2.0 * mean * sy + mean * mean * nf) / denom;
    var = fmax(var, 1e-12);

    const double diff_bits = (nf > 1.0) ? nf * (LOG2_2PIE + 0.5 * log2(var)) : 0.0;
    const double jac_bits  = slj / LN2;
    const double rres      = (double)resolutions[f];
    const double exc_bits  = (nexc > 0.0) ? nexc * (-log2(rres)) : 0.0;
    const double log_binom = lgamma(Bd + 1.0) - lgamma(nexc + 1.0)
                           - lgamma(Bd - nexc + 1.0);
    const double part_bits = (nexc > 0.0 && nexc < Bd) ? (log_binom / LN2) : 0.0;
    const double lambda_bits = 2.0 * (log(100.0) / LN2);

    double tot = diff_bits + jac_bits + exc_bits + part_bits + lambda_bits;

    __shared__ double sh[F];
    sh[f] = tot;
    __syncthreads();
#pragma unroll
    for (int s = 128; s > 0; s >>= 1) {
        if (f < s) sh[f] += sh[f + s];
        __syncthreads();
    }
    if (f == 0) out[0] = (float)sh[0];
}

extern "C" void kernel_launch(void* const* d_in, const int* in_sizes, int n_in,
                              void* d_out, int out_size)
{
    const float* residuals   = (const float*)d_in[0];
    const float* lambda1     = (const float*)d_in[1];
    const float* lambda2     = (const float*)d_in[2];
    const float* resolutions = (const float*)d_in[3];
    float* out = (float*)d_out;

    const int B = in_sizes[0] / F;
    const int rows_per_block = (B + NB - 1) / NB;

    mdl_pass1<<<NB, 256>>>(residuals, lambda1, lambda2, rows_per_block, B);
    mdl_pass2<<<1, 256>>>(resolutions, out, B);
}

// round 2
// speedup vs baseline: 2.4336x; 2.4336x over previous
#include <cuda_runtime.h>
#include <math.h>

#define F 256
#define NB 1024
#define NB2 32           // pass2a blocks; each reduces NB/NB2 = 32 partial rows

// Stage-1 partials: [4][NB][F] floats = 4 MB
__device__ float  g_part [4 * NB  * F];
// Stage-2 partials: [4][NB2][F] doubles = 256 KB
__device__ double g_part2[4 * NB2 * F];

__global__ __launch_bounds__(256) void mdl_pass1(
    const float* __restrict__ res,
    const float* __restrict__ lambda1,
    const float* __restrict__ lambda2,
    int rows_per_block, int B)
{
    const int f = threadIdx.x;            // feature index 0..255
    const float l1  = lambda1[f];
    const float l2v = lambda2[f];
    const float lamP = l1;
    const float lamN = 2.0f - l2v;
    const float rlamP = 1.0f / lamP;
    const float rlamN = 1.0f / lamN;
    const bool okP = fabsf(l1)  <= 1.9f;
    const bool okN = fabsf(l2v) <= 1.9f;
    const bool tinyP = fabsf(lamP) < 1e-8f;
    const bool tinyN = fabsf(lamN) < 1e-8f;

    const int r0 = blockIdx.x * rows_per_block;
    int r1 = r0 + rows_per_block;
    if (r1 > B) r1 = B;

    float cnt = 0.0f, sy = 0.0f, sy2 = 0.0f, slj = 0.0f;

    const float* p = res + (size_t)r0 * F + f;

#pragma unroll 8
    for (int r = r0; r < r1; ++r, p += F) {
        const float x = *p;
        const bool pos = (x >= 0.0f);

        // unified transform:
        //   pos: a = 1 + min(x,1000),  lam = lambda1,      y = +expm1(lam*t)/lam
        //   neg: a = 1 - max(x,-.989), lam = 2 - lambda2,  y = -expm1(lam*t)/lam
        //   lj  = (lam - 1) * t  in both branches
        const float a    = pos ? (1.0f + fminf(x, 1000.0f))
                               : (1.0f - fmaxf(x, -0.989f));
        const float lam  = pos ? lamP : lamN;
        const float rlam = pos ? rlamP : rlamN;
        const bool tiny  = pos ? tinyP : tinyN;
        const bool safe  = pos ? ((x <= 1000.0f) && okP)
                               : ((x > -0.99f) && okN);

        const float t = __logf(a);
        const float u = lam * t;

        // branchless expm1: Taylor for small |u|, __expf path otherwise
        const float e_poly = u * (1.0f + u * (0.5f + u * (0.16666667f
                              + u * (0.041666668f + u * 0.008333334f))));
        const float e_exp  = __expf(u) - 1.0f;
        const float e = (fabsf(u) < 0.25f) ? e_poly : e_exp;

        float y = tiny ? t : (e * rlam);
        if (!pos) y = -y;
        const float lj = (lam - 1.0f) * t;

        if (safe) {
            cnt += 1.0f;
            sy  += y;
            sy2 += y * y;
            slj += lj;
        }
    }

    const int base = blockIdx.x * F + f;
    g_part[0 * NB * F + base] = cnt;
    g_part[1 * NB * F + base] = sy;
    g_part[2 * NB * F + base] = sy2;
    g_part[3 * NB * F + base] = slj;
}

// Reduce 1024 partial rows -> 32, coalesced (thread = feature), double accum.
__global__ __launch_bounds__(256) void mdl_pass2a()
{
    const int f = threadIdx.x;
    const int j = blockIdx.x;               // 0..NB2-1
    const int b0 = j * (NB / NB2);

    double a0 = 0.0, a1 = 0.0, a2 = 0.0, a3 = 0.0;
#pragma unroll 8
    for (int b = b0; b < b0 + (NB / NB2); ++b) {
        const int base = b * F + f;
        a0 += (double)g_part[0 * NB * F + base];
        a1 += (double)g_part[1 * NB * F + base];
        a2 += (double)g_part[2 * NB * F + base];
        a3 += (double)g_part[3 * NB * F + base];
    }
    const int o = j * F + f;
    g_part2[0 * NB2 * F + o] = a0;
    g_part2[1 * NB2 * F + o] = a1;
    g_part2[2 * NB2 * F + o] = a2;
    g_part2[3 * NB2 * F + o] = a3;
}

__global__ __launch_bounds__(256) void mdl_pass2b(
    const float* __restrict__ resolutions,
    float* __restrict__ out, int B)
{
    const int f = threadIdx.x;  // one feature per thread

    double cnt = 0.0, sy = 0.0, sy2 = 0.0, slj = 0.0;
#pragma unroll
    for (int b = 0; b < NB2; ++b) {
        const int base = b * F + f;
        cnt += g_part2[0 * NB2 * F + base];
        sy  += g_part2[1 * NB2 * F + base];
        sy2 += g_part2[2 * NB2 * F + base];
        slj += g_part2[3 * NB2 * F + base];
    }

    const double LN2 = 0.6931471805599453;
    const double LOG2_2PIE = 2.0470955851806783;  // 0.5*log2(2*pi*e)

    const double Bd   = (double)B;
    const double nf   = cnt;
    const double nexc = Bd - nf;
    const double denom = fmax(nf, 1.0);
    const double mean = sy / denom;
    double var = (sy2 - 2.0 * mean * sy + mean * mean * nf) / denom;
    var = fmax(var, 1e-12);

    const double diff_bits = (nf > 1.0) ? nf * (LOG2_2PIE + 0.5 * log2(var)) : 0.0;
    const double jac_bits  = slj / LN2;
    const double rres      = (double)resolutions[f];
    const double exc_bits  = (nexc > 0.0) ? nexc * (-log2(rres)) : 0.0;
    const double log_binom = lgamma(Bd + 1.0) - lgamma(nexc + 1.0)
                           - lgamma(Bd - nexc + 1.0);
    const double part_bits = (nexc > 0.0 && nexc < Bd) ? (log_binom / LN2) : 0.0;
    const double lambda_bits = 2.0 * (log(100.0) / LN2);

    double tot = diff_bits + jac_bits + exc_bits + part_bits + lambda_bits;

    __shared__ double sh[F];
    sh[f] = tot;
    __syncthreads();
#pragma unroll
    for (int s = 128; s > 0; s >>= 1) {
        if (f < s) sh[f] += sh[f + s];
        __syncthreads();
    }
    if (f == 0) out[0] = (float)sh[0];
}

extern "C" void kernel_launch(void* const* d_in, const int* in_sizes, int n_in,
                              void* d_out, int out_size)
{
    const float* residuals   = (const float*)d_in[0];
    const float* lambda1     = (const float*)d_in[1];
    const float* lambda2     = (const float*)d_in[2];
    const float* resolutions = (const float*)d_in[3];
    float* out = (float*)d_out;

    const int B = in_sizes[0] / F;
    const int rows_per_block = (B + NB - 1) / NB;

    mdl_pass1<<<NB, 256>>>(residuals, lambda1, lambda2, rows_per_block, B);
    mdl_pass2a<<<NB2, 256>>>();
    mdl_pass2b<<<1, 256>>>(resolutions, out, B);
}

// round 3
// speedup vs baseline: 3.7243x; 1.5303x over previous
#include <cuda_runtime.h>
#include <math.h>

#define F 256
#define NB 1024

// Stage-1 partials, transposed: [4 acc][F][NB] floats = 4 MB
__device__ float  g_part[4 * F * NB];
// Per-feature bits
__device__ double g_bits[F];

__device__ __forceinline__ float fast_lg2(float a) {
    float r; asm("lg2.approx.f32 %0, %1;" : "=f"(r) : "f"(a)); return r;
}
__device__ __forceinline__ float fast_ex2(float a) {
    float r; asm("ex2.approx.f32 %0, %1;" : "=f"(r) : "f"(a)); return r;
}

__global__ __launch_bounds__(256) void mdl_pass1(
    const float* __restrict__ res,
    const float* __restrict__ lambda1,
    const float* __restrict__ lambda2,
    int rows_per_block, int B)
{
    const int f = threadIdx.x;            // feature 0..255
    const float l1 = lambda1[f];
    const float l2 = lambda2[f];
    // clamp lambdas away from 0 so the Taylor path handles the "tiny" case
    float lamP = (fabsf(l1) < 1e-8f) ? 1e-8f : l1;
    float lamN = 2.0f - l2;
    if (fabsf(lamN) < 1e-8f) lamN = 1e-8f;
    const float rlamP  =  1.0f / lamP;
    const float nrlamN = -1.0f / lamN;
    // per-side safe bound folded with the uniform |lambda|<=1.9 check
    const float bsP = (fabsf(l1) <= 1.9f) ? 1000.0f : -1.0f;
    const float bsN = (fabsf(l2) <= 1.9f) ? 0.99f   : -1.0f;

    const int r0 = blockIdx.x * rows_per_block;
    int r1 = r0 + rows_per_block;
    if (r1 > B) r1 = B;

    float cnt = 0.0f, sy = 0.0f, sy2 = 0.0f, slj2 = 0.0f;
    const float* p = res + (size_t)r0 * F + f;
    const float LN2F = 0.69314718056f;

#pragma unroll 8
    for (int r = r0; r < r1; ++r, p += F) {
        const float x = *p;
        const bool pos = (x >= 0.0f);
        const float ax = fabsf(x);
        const float bc  = pos ? 1000.0f : 0.989f;   // clip bound
        const float lam = pos ? lamP    : lamN;
        const float rl  = pos ? rlamP   : nrlamN;   // sign folded in
        const float bs  = pos ? bsP     : bsN;      // safety bound

        const float a  = 1.0f + fminf(ax, bc);
        const float t2 = fast_lg2(a);               // log2(1+|x|clip)
        const float u2 = lam * t2;
        const float u  = u2 * LN2F;                 // natural lam*t

        // expm1(u): Taylor for small |u| (cancellation), ex2 otherwise
        const float ep = u * (1.0f + u * (0.5f + u * (0.16666667f
                           + u * (0.041666668f + u * 0.008333334f))));
        const float ee = fast_ex2(u2) - 1.0f;
        const float e  = (fabsf(u) < 0.25f) ? ep : ee;

        const float y   = e * rl;
        const float lj2 = u2 - t2;                  // (lam-1)*log2(.) == log_jac/LN2

        if (ax <= bs) {
            cnt  += 1.0f;
            sy   += y;
            sy2   = fmaf(y, y, sy2);
            slj2 += lj2;
        }
    }

    const int idx = f * NB + blockIdx.x;            // transposed store
    g_part[0 * F * NB + idx] = cnt;
    g_part[1 * F * NB + idx] = sy;
    g_part[2 * F * NB + idx] = sy2;
    g_part[3 * F * NB + idx] = slj2;
}

// 32 blocks x 256 threads: warp w of block j owns feature gf = j*8+w.
// Coalesced reads of the [F][NB] rows, warp-shuffle reduce, then the full
// per-feature double-precision bit computation.
__global__ __launch_bounds__(256) void mdl_pass2a(
    const float* __restrict__ resolutions, int B)
{
    const int gf   = blockIdx.x * 8 + (threadIdx.x >> 5);
    const int lane = threadIdx.x & 31;
    const float* b0 = g_part + (size_t)gf * NB;

    double cnt = 0.0, sy = 0.0, sy2 = 0.0, slj = 0.0;
#pragma unroll 8
    for (int b = lane; b < NB; b += 32) {
        cnt += (double)b0[b];
        sy  += (double)b0[1 * F * NB + b];
        sy2 += (double)b0[2 * F * NB + b];
        slj += (double)b0[3 * F * NB + b];
    }
#pragma unroll
    for (int o = 16; o > 0; o >>= 1) {
        cnt += __shfl_down_sync(0xffffffffu, cnt, o);
        sy  += __shfl_down_sync(0xffffffffu, sy,  o);
        sy2 += __shfl_down_sync(0xffffffffu, sy2, o);
        slj += __shfl_down_sync(0xffffffffu, slj, o);
    }

    if (lane == 0) {
        const double LN2 = 0.6931471805599453;
        const double LOG2_2PIE = 2.0470955851806783;

        const double Bd    = (double)B;
        const double nf    = cnt;
        const double nexc  = Bd - nf;
        const double denom = fmax(nf, 1.0);
        const double mean  = sy / denom;
        double var = (sy2 - 2.0 * mean * sy + mean * mean * nf) / denom;
        var = fmax(var, 1e-12);

        const double diff_bits = (nf > 1.0) ? nf * (LOG2_2PIE + 0.5 * log2(var)) : 0.0;
        const double jac_bits  = slj;  // already accumulated in log2 units
        const double rres      = (double)resolutions[gf];
        const double exc_bits  = (nexc > 0.0) ? nexc * (-log2(rres)) : 0.0;
        const double log_binom = lgamma(Bd + 1.0) - lgamma(nexc + 1.0)
                               - lgamma(Bd - nexc + 1.0);
        const double part_bits = (nexc > 0.0 && nexc < Bd) ? (log_binom / LN2) : 0.0;
        const double lambda_bits = 2.0 * (log(100.0) / LN2);

        g_bits[gf] = diff_bits + jac_bits + exc_bits + part_bits + lambda_bits;
    }
}

__global__ __launch_bounds__(256) void mdl_pass2b(float* __restrict__ out)
{
    const int f = threadIdx.x;
    __shared__ double sh[F];
    sh[f] = g_bits[f];
    __syncthreads();
#pragma unroll
    for (int s = 128; s > 0; s >>= 1) {
        if (f < s) sh[f] += sh[f + s];
        __syncthreads();
    }
    if (f == 0) out[0] = (float)sh[0];
}

extern "C" void kernel_launch(void* const* d_in, const int* in_sizes, int n_in,
                              void* d_out, int out_size)
{
    const float* residuals   = (const float*)d_in[0];
    const float* lambda1     = (const float*)d_in[1];
    const float* lambda2     = (const float*)d_in[2];
    const float* resolutions = (const float*)d_in[3];
    float* out = (float*)d_out;

    const int B = in_sizes[0] / F;
    const int rows_per_block = (B + NB - 1) / NB;

    mdl_pass1<<<NB, 256>>>(residuals, lambda1, lambda2, rows_per_block, B);
    mdl_pass2a<<<F / 8, 256>>>(resolutions, B);
    mdl_pass2b<<<1, 256>>>(out);
}